// round 4
// baseline (speedup 1.0000x reference)
#include <cuda_runtime.h>

// GAE backward scan, round 4: smaller chunks for higher occupancy.
// adv[t] = delta[t] + GL*adv[t+1],  delta[t] = r[t] + GAMMA*v[t+1] - v[t]
// 32 time-chunks x 256 column-groups = 8192 blocks. local[32] keeps regs ~60
// -> ~8 blocks/SM (~50% occ) vs 5 (29.5%) in round 3. Lookback depth <=31,
// scratch (4MB) stays L2-resident. Boundary predication only in last chunk.

#define B_COLS 32768
#define TM1 1023            // output rows t = 0 .. 1022
#define GAMMA 0.99f
#define GL (0.99f * 0.95f)
#define NCHUNK 32
#define RMAX 32             // rows per chunk (last chunk: 31 valid)
#define GBLK 256            // column groups (B_COLS / 128)

__device__ float g_scratch[NCHUNK * B_COLS];  // C_k per (chunk, column)
__device__ int   g_flags[NCHUNK * GBLK];      // publish flags
__device__ int   g_ticket;                    // ordered tile assignment

__global__ void reset_kernel() {
    int i = blockIdx.x * blockDim.x + threadIdx.x;
    if (i < NCHUNK * GBLK) g_flags[i] = 0;
    if (i == 0) g_ticket = 0;
}

__global__ __launch_bounds__(128) void gae_chunk_kernel(
    const float* __restrict__ rewards,
    const float* __restrict__ values,
    float* __restrict__ out)
{
    __shared__ int s_ticket;
    if (threadIdx.x == 0) s_ticket = atomicAdd(&g_ticket, 1);
    __syncthreads();
    const int ticket = s_ticket;
    const int k  = ticket >> 8;          // chunk index 0..31 (0 = highest t)
    const int gx = ticket & 255;         // column group
    const int c  = gx * 128 + threadIdx.x;
    const int t_hi = (TM1 - 1) - RMAX * k;   // 1022 - 32k

    const float* r = rewards + c;
    const float* v = values + c;
    float* o = out + c;

    // ---- local backward scan (carry-in = 0), 32 rows, batched loads ----
    float local[RMAX];
    float acc = 0.0f;
    float v_next = __ldcs(v + (t_hi + 1) * B_COLS);

    if (k < NCHUNK - 1) {
        // Fast path: all rows valid, no predication.
        #pragma unroll
        for (int g0 = 0; g0 < RMAX; g0 += 8) {
            float rt[8], vt[8];
            #pragma unroll
            for (int i = 0; i < 8; ++i) {
                const int t = t_hi - (g0 + i);
                rt[i] = __ldcs(r + t * B_COLS);
                vt[i] = __ldcs(v + t * B_COLS);
            }
            #pragma unroll
            for (int i = 0; i < 8; ++i) {
                const float delta = fmaf(GAMMA, v_next, rt[i]) - vt[i];
                acc = fmaf(GL, acc, delta);
                local[g0 + i] = acc;
                v_next = vt[i];
            }
        }
        // publish chunk-sum C_k
        g_scratch[k * B_COLS + c] = local[RMAX - 1];
        __threadfence();
        __syncthreads();
        if (threadIdx.x == 0) atomicExch(&g_flags[k * GBLK + gx], 1);
    } else {
        // Last chunk (k=31): t goes 30..0, row 31 is invalid. No consumers -> no publish.
        #pragma unroll
        for (int g0 = 0; g0 < RMAX; g0 += 8) {
            float rt[8], vt[8];
            #pragma unroll
            for (int i = 0; i < 8; ++i) {
                const int t = t_hi - (g0 + i);
                if (t >= 0) {
                    rt[i] = __ldcs(r + t * B_COLS);
                    vt[i] = __ldcs(v + t * B_COLS);
                } else { rt[i] = 0.0f; vt[i] = 0.0f; }
            }
            #pragma unroll
            for (int i = 0; i < 8; ++i) {
                const float delta = fmaf(GAMMA, v_next, rt[i]) - vt[i];
                acc = fmaf(GL, acc, delta);
                local[g0 + i] = acc;
                v_next = vt[i];
            }
        }
    }

    // ---- lookback: A = sum_{j<k} C_j * gl^(RMAX*(k-1-j)) ----
    float A = 0.0f;
    if (k > 0) {
        if (threadIdx.x < k) {  // thread j spins on predecessor j's flag
            while (atomicAdd(&g_flags[threadIdx.x * GBLK + gx], 0) == 0) {}
        }
        __syncthreads();

        // gl^32 via 5 squarings
        const float g2 = GL * GL, g4 = g2 * g2, g8 = g4 * g4;
        const float g16 = g8 * g8, gl32 = g16 * g16;

        float w = 1.0f;
        for (int j = k - 1; j >= 0; --j) {
            const float Cj = __ldcg(&g_scratch[j * B_COLS + c]);
            A = fmaf(Cj, w, A);
            w *= gl32;
        }
    }

    // ---- fixup + store: adv[t_hi - i] = local[i] + A * gl^(i+1) ----
    float Ai = A;
    if (k < NCHUNK - 1) {
        #pragma unroll
        for (int i = 0; i < RMAX; ++i) {
            Ai *= GL;
            __stcs(o + (t_hi - i) * B_COLS, fmaf(Ai, 1.0f, local[i]));
        }
    } else {
        #pragma unroll
        for (int i = 0; i < RMAX; ++i) {
            const int t = t_hi - i;
            Ai *= GL;
            if (t >= 0) __stcs(o + t * B_COLS, local[i] + Ai);
        }
    }
}

extern "C" void kernel_launch(void* const* d_in, const int* in_sizes, int n_in,
                              void* d_out, int out_size) {
    const float* rewards = (const float*)d_in[0];
    const float* values  = (const float*)d_in[1];
    float* out = (float*)d_out;

    reset_kernel<<<32, 256>>>();
    gae_chunk_kernel<<<NCHUNK * GBLK, 128>>>(rewards, values, out);
}

// round 5
// speedup vs baseline: 1.0561x; 1.0561x over previous
#include <cuda_runtime.h>

// GAE backward scan, round 5: truncated lookback (exponential forgetting) +
// float2-vectorized loads/stores.
// adv[t] = delta[t] + GL*adv[t+1],  delta[t] = r[t] + GAMMA*v[t+1] - v[t]
// gl^(32*8) ~= 1.5e-7 -> lookback beyond 8 predecessor chunks is below fp32
// rounding noise; truncate there. Each thread owns 2 adjacent columns (LDG.64),
// doubling bytes-in-flight per scoreboard slot and halving LSU instruction count.

#define B_COLS 32768
#define TM1 1023            // output rows t = 0 .. 1022
#define GAMMA 0.99f
#define GL (0.99f * 0.95f)
#define NCHUNK 32
#define RMAX 32             // rows per chunk (last chunk: 31 valid)
#define GBLK 128            // column groups of 256 columns (B_COLS / 256)
#define DEPTH 8             // truncated lookback depth: gl^(32*8) ~ 1.5e-7

__device__ float g_scratch[NCHUNK * B_COLS];  // C_k per (chunk, column)
__device__ int   g_flags[NCHUNK * GBLK];      // publish flags
__device__ int   g_ticket;                    // ordered tile assignment

__global__ void reset_kernel() {
    int i = blockIdx.x * blockDim.x + threadIdx.x;
    if (i < NCHUNK * GBLK) g_flags[i] = 0;
    if (i == 0) g_ticket = 0;
}

__global__ __launch_bounds__(128) void gae_chunk_kernel(
    const float* __restrict__ rewards,
    const float* __restrict__ values,
    float* __restrict__ out)
{
    __shared__ int s_ticket;
    if (threadIdx.x == 0) s_ticket = atomicAdd(&g_ticket, 1);
    __syncthreads();
    const int ticket = s_ticket;
    const int k  = ticket >> 7;          // chunk index 0..31 (0 = highest t)
    const int gx = ticket & (GBLK - 1);  // column group
    // Each thread owns 2 adjacent columns: float2 index within a row.
    const int c2 = gx * 128 + threadIdx.x;       // float2 column index (0..16383)
    const int ROW2 = B_COLS / 2;                  // row stride in float2 units
    const int t_hi = (TM1 - 1) - RMAX * k;        // 1022 - 32k

    const float2* r = (const float2*)rewards + c2;
    const float2* v = (const float2*)values + c2;
    float2* o = (float2*)out + c2;

    // ---- local backward scan (carry-in = 0), 32 rows, batched LDG.64 ----
    float2 local[RMAX];
    float ax = 0.0f, ay = 0.0f;
    float2 vn = __ldcs(v + (t_hi + 1) * ROW2);

    if (k < NCHUNK - 1) {
        // Fast path: all rows valid, no predication.
        #pragma unroll
        for (int g0 = 0; g0 < RMAX; g0 += 8) {
            float2 rt[8], vt[8];
            #pragma unroll
            for (int i = 0; i < 8; ++i) {
                const int t = t_hi - (g0 + i);
                rt[i] = __ldcs(r + t * ROW2);
                vt[i] = __ldcs(v + t * ROW2);
            }
            #pragma unroll
            for (int i = 0; i < 8; ++i) {
                const float dx = fmaf(GAMMA, vn.x, rt[i].x) - vt[i].x;
                const float dy = fmaf(GAMMA, vn.y, rt[i].y) - vt[i].y;
                ax = fmaf(GL, ax, dx);
                ay = fmaf(GL, ay, dy);
                local[g0 + i] = make_float2(ax, ay);
                vn = vt[i];
            }
        }
        // publish chunk-sum C_k
        *(float2*)&g_scratch[k * B_COLS + 2 * c2] = local[RMAX - 1];
        __threadfence();
        __syncthreads();
        if (threadIdx.x == 0) atomicExch(&g_flags[k * GBLK + gx], 1);
    } else {
        // Last chunk (k=31): t goes 30..0; row index 31 is invalid. No consumers.
        #pragma unroll
        for (int g0 = 0; g0 < RMAX; g0 += 8) {
            float2 rt[8], vt[8];
            #pragma unroll
            for (int i = 0; i < 8; ++i) {
                const int t = t_hi - (g0 + i);
                if (t >= 0) {
                    rt[i] = __ldcs(r + t * ROW2);
                    vt[i] = __ldcs(v + t * ROW2);
                } else {
                    rt[i] = make_float2(0.0f, 0.0f);
                    vt[i] = make_float2(0.0f, 0.0f);
                }
            }
            #pragma unroll
            for (int i = 0; i < 8; ++i) {
                const float dx = fmaf(GAMMA, vn.x, rt[i].x) - vt[i].x;
                const float dy = fmaf(GAMMA, vn.y, rt[i].y) - vt[i].y;
                ax = fmaf(GL, ax, dx);
                ay = fmaf(GL, ay, dy);
                local[g0 + i] = make_float2(ax, ay);
                vn = vt[i];
            }
        }
    }

    // ---- truncated lookback: A = sum_{j=k-1 .. k-DEPTH} C_j * gl^(32*(k-1-j)) ----
    float Ax = 0.0f, Ay = 0.0f;
    if (k > 0) {
        const int d = (k < DEPTH) ? k : DEPTH;
        if (threadIdx.x < d) {  // thread i spins on predecessor (k-1-i)'s flag
            while (atomicAdd(&g_flags[(k - 1 - threadIdx.x) * GBLK + gx], 0) == 0) {}
        }
        __syncthreads();

        // gl^32 via 5 squarings
        const float g2 = GL * GL, g4 = g2 * g2, g8 = g4 * g4;
        const float g16 = g8 * g8, gl32 = g16 * g16;

        float w = 1.0f;
        for (int j = k - 1; j >= k - d; --j) {
            const float2 Cj = *(const float2*)&g_scratch[j * B_COLS + 2 * c2];
            Ax = fmaf(Cj.x, w, Ax);
            Ay = fmaf(Cj.y, w, Ay);
            w *= gl32;
        }
    }

    // ---- fixup + store: adv[t_hi - i] = local[i] + A * gl^(i+1) ----
    if (k < NCHUNK - 1) {
        #pragma unroll
        for (int i = 0; i < RMAX; ++i) {
            Ax *= GL;
            Ay *= GL;
            __stcs(o + (t_hi - i) * ROW2,
                   make_float2(local[i].x + Ax, local[i].y + Ay));
        }
    } else {
        #pragma unroll
        for (int i = 0; i < RMAX; ++i) {
            const int t = t_hi - i;
            Ax *= GL;
            Ay *= GL;
            if (t >= 0)
                __stcs(o + t * ROW2,
                       make_float2(local[i].x + Ax, local[i].y + Ay));
        }
    }
}

extern "C" void kernel_launch(void* const* d_in, const int* in_sizes, int n_in,
                              void* d_out, int out_size) {
    const float* rewards = (const float*)d_in[0];
    const float* values  = (const float*)d_in[1];
    float* out = (float*)d_out;

    reset_kernel<<<32, 128>>>();
    gae_chunk_kernel<<<NCHUNK * GBLK, 128>>>(rewards, values, out);
}